// round 9
// baseline (speedup 1.0000x reference)
#include <cuda_runtime.h>
#include <cstdint>

// ----------------------------------------------------------------------------
// GCN_8796093022507: 2-layer GCN, N=100000 nodes, E=6.4M edges.
// Layer math factorizes to scalar-per-node aggregations (x is [N,1]).
// Dropout reproduces JAX threefry2x32 with threefry_partitionable=True:
//   random_bits(32) elem j = y0 ^ y1 of threefry(key, (0, j))   (XOR combine)
//   split(key)[i]          = (y0, y1) of threefry(key, (0, i))  (foldlike)
// edge_index is int32 on device (JAX x64 disabled downgrades int64).
// ----------------------------------------------------------------------------

#define N_MAX 100352   // >= N, padded

__device__ int   g_deg [N_MAX];
__device__ float g_dinv[N_MAX];
__device__ float g_t1  [N_MAX];   // dinv[src]*xd[src]   (layer-1 source values)
__device__ float g_acc1[N_MAX];   // scatter target, layer 1
__device__ float g_t2  [N_MAX];   // dinv[src]*s[src]    (layer-2 source values)
__device__ float g_acc2[N_MAX];   // scatter target, layer 2

// --- JAX threefry2x32 (20 rounds), host+device ------------------------------
__host__ __device__ inline void tf2x32(uint32_t k0, uint32_t k1,
                                       uint32_t x0, uint32_t x1,
                                       uint32_t& y0, uint32_t& y1)
{
    uint32_t ks2 = k0 ^ k1 ^ 0x1BD11BDAu;
    x0 += k0; x1 += k1;
#define TFR(r) { x0 += x1; x1 = (x1 << (r)) | (x1 >> (32 - (r))); x1 ^= x0; }
    TFR(13) TFR(15) TFR(26) TFR(6)
    x0 += k1;  x1 += ks2 + 1u;
    TFR(17) TFR(29) TFR(16) TFR(24)
    x0 += ks2; x1 += k0 + 2u;
    TFR(13) TFR(15) TFR(26) TFR(6)
    x0 += k0;  x1 += k1 + 3u;
    TFR(17) TFR(29) TFR(16) TFR(24)
    x0 += k1;  x1 += ks2 + 4u;
    TFR(13) TFR(15) TFR(26) TFR(6)
    x0 += ks2; x1 += k0 + 5u;
#undef TFR
    y0 = x0; y1 = x1;
}

// Partitionable random_bits(32) for flat index j (< 2^32): counter (0, j),
// result = y0 ^ y1.
__device__ __forceinline__ uint32_t rbits(uint32_t k0, uint32_t k1, uint32_t j) {
    uint32_t y0, y1;
    tf2x32(k0, k1, 0u, j, y0, y1);
    return y0 ^ y1;
}

__device__ __forceinline__ float u01(uint32_t bits) {
    // JAX uniform: bitcast((bits>>9)|0x3f800000) - 1.0
    return __uint_as_float((bits >> 9) | 0x3f800000u) - 1.0f;
}

// --- kernels ----------------------------------------------------------------

__global__ void k_zero(int N) {
    int i = blockIdx.x * blockDim.x + threadIdx.x;
    if (i < N) { g_deg[i] = 0; g_acc1[i] = 0.0f; g_acc2[i] = 0.0f; }
}

// In-degree: one atomic int add per edge (compiles to RED — no return)
__global__ void k_deg(const int* __restrict__ dst, int E) {
    int base = (blockIdx.x * blockDim.x + threadIdx.x) * 4;
    if (base + 4 <= E) {
        int4 d = __ldg((const int4*)(dst + base));
        atomicAdd(&g_deg[d.x], 1);
        atomicAdd(&g_deg[d.y], 1);
        atomicAdd(&g_deg[d.z], 1);
        atomicAdd(&g_deg[d.w], 1);
    } else {
        for (int e = base; e < E; ++e)
            atomicAdd(&g_deg[__ldg(dst + e)], 1);
    }
}

// dinv + dropout1(x) + premultiplied source value t1 = dinv*xd.
__global__ void k_nodeA(const float* __restrict__ x, int N,
                        uint32_t k0, uint32_t k1) {
    int i = blockIdx.x * blockDim.x + threadIdx.x;
    if (i >= N) return;

    int dg = g_deg[i];
    float dv = (dg > 0) ? rsqrtf((float)dg) : 0.0f;
    g_dinv[i] = dv;

    float xv = __ldg(&x[i]);
    float xd = (u01(rbits(k0, k1, (uint32_t)i)) < 0.4f) ? xv / 0.4f : 0.0f;
    g_t1[i] = dv * xd;
}

// Scalar edge aggregation: acc[dst] += t[src]  (gather + RED.F32, both L2-hit)
template <int PASS>
__global__ void k_agg(const int* __restrict__ src,
                      const int* __restrict__ dst, int E) {
    const float* __restrict__ t   = (PASS == 1) ? g_t1   : g_t2;
    float*       __restrict__ acc = (PASS == 1) ? g_acc1 : g_acc2;
    int base = (blockIdx.x * blockDim.x + threadIdx.x) * 4;
    if (base + 4 <= E) {
        int4 s = __ldg((const int4*)(src + base));
        int4 d = __ldg((const int4*)(dst + base));
        float v0 = __ldg(&t[s.x]);
        float v1 = __ldg(&t[s.y]);
        float v2 = __ldg(&t[s.z]);
        float v3 = __ldg(&t[s.w]);
        atomicAdd(&acc[d.x], v0);
        atomicAdd(&acc[d.y], v1);
        atomicAdd(&acc[d.z], v2);
        atomicAdd(&acc[d.w], v3);
    } else {
        for (int e = base; e < E; ++e)
            atomicAdd(&acc[__ldg(dst + e)], __ldg(&t[__ldg(src + e)]));
    }
}

// Layer-1 finish + relu + dropout2 + (·W2) collapse to scalar s; t2 = dinv*s.
// Dropout2 flat element index j = n*16+c over shape (N,16).
__global__ void k_nodeC(const float* __restrict__ W1, const float* __restrict__ b1,
                        const float* __restrict__ W2, int N,
                        uint32_t k0, uint32_t k1) {
    int i = blockIdx.x * blockDim.x + threadIdx.x;
    if (i >= N) return;

    float a = g_dinv[i] * g_acc1[i];
    float s = 0.0f;

#pragma unroll
    for (int c = 0; c < 16; ++c) {
        uint32_t j = (uint32_t)i * 16u + (uint32_t)c;
        float w  = __ldg(&W1[c]);
        float bb = __ldg(&b1[c]);
        float w2 = __ldg(&W2[c]);
        float h  = fmaxf(w * a + bb, 0.0f);
        if (u01(rbits(k0, k1, j)) < 0.4f) s += (h / 0.4f) * w2;
    }
    g_t2[i] = g_dinv[i] * s;
}

__global__ void k_nodeE(float* __restrict__ out, const float* __restrict__ b2, int N) {
    int i = blockIdx.x * blockDim.x + threadIdx.x;
    if (i < N) out[i] = g_dinv[i] * g_acc2[i] + __ldg(&b2[0]);
}

// --- launch -----------------------------------------------------------------

extern "C" void kernel_launch(void* const* d_in, const int* in_sizes, int n_in,
                              void* d_out, int out_size) {
    const float* x  = (const float*)d_in[0];
    const int*   ei = (const int*)d_in[1];     // int32 on device
    const float* W1 = (const float*)d_in[2];
    const float* b1 = (const float*)d_in[3];
    const float* W2 = (const float*)d_in[4];
    const float* b2 = (const float*)d_in[5];
    int N = in_sizes[0];
    int E = in_sizes[1] / 2;
    const int* src = ei;
    const int* dst = ei + E;

    // Foldlike split of key(42)=(0,42): child i = (y0,y1) of counter (0, i).
    uint32_t key1_0, key1_1, key2_0, key2_1;
    tf2x32(0u, 42u, 0u, 0u, key1_0, key1_1);   // dropout 1 key
    tf2x32(0u, 42u, 0u, 1u, key2_0, key2_1);   // dropout 2 key

    const int T = 256;
    int eThreads = (E + 3) / 4;
    unsigned eBlocks = (unsigned)((eThreads + T - 1) / T);
    unsigned nBlocks = (unsigned)((N + T - 1) / T);

    k_zero  <<<nBlocks, T>>>(N);
    k_deg   <<<eBlocks, T>>>(dst, E);
    k_nodeA <<<nBlocks, T>>>(x, N, key1_0, key1_1);
    k_agg<1><<<eBlocks, T>>>(src, dst, E);
    k_nodeC <<<nBlocks, T>>>(W1, b1, W2, N, key2_0, key2_1);
    k_agg<2><<<eBlocks, T>>>(src, dst, E);
    k_nodeE <<<nBlocks, T>>>((float*)d_out, b2, N);
}